// round 13
// baseline (speedup 1.0000x reference)
#include <cuda_runtime.h>
#include <cuda_fp16.h>
#include <cstdint>

// QuantizedLinear on GB300 (sm_103a harness, compute_103 virtual arch -> legacy
// mma.sync.m16n8k16 path; tcgen05 PTX rejected by ptxas at this target).
//   y[b,o] = scale[o] * sum_k x[b,k] * (q[o,k] - 8)
//
// Round 12 = Round 11 (best: in-GEMM W dequant from raw packed words via
// smem staging with self-owned segments) + dequant INTERLEAVED into the kk
// loop (2 segs after each HMMA sub-block) so its ~112 instructions fill
// tensor-pipe shadows instead of clumping before the barrier.
// Prep = x->fp16 only (8 MB). No W prepass.

static constexpr int M_DIM = 512;
static constexpr int N_DIM = 8192;
static constexpr int K_DIM = 8192;
static constexpr int KWORDS = K_DIM / 2;           // packed words per W row

static constexpr int BM = 128;
static constexpr int BN = 128;
static constexpr int KC = 64;
static constexpr int ASTAGES = 3;
static constexpr int NCHUNK = K_DIM / KC;          // 128
static constexpr int NTHREADS = 128;               // 4 warps, 2x2 of 64x64

static constexpr int A_BYTES  = BM * 128;          // 16 KB fp16 SW128
static constexpr int BP_BYTES = BN * 128;          // 16 KB packed (flat)
static constexpr int BF_BYTES = BN * 128;          // 16 KB fp16 SW128
// layout: A[3] | Bp[2] | Bf[2]
static constexpr int OFF_BP = ASTAGES * A_BYTES;            // 49152
static constexpr int OFF_BF = OFF_BP + 2 * BP_BYTES;        // 81920
static constexpr int SMEM_BYTES = OFF_BF + 2 * BF_BYTES;    // 114688 -> 2 CTAs/SM

static constexpr int XCONV_BLOCKS = (M_DIM * K_DIM / 4) / 256;   // 4096

// -------- scratch (device global; no runtime allocation) --------
__device__ __align__(16) __half g_xh[(size_t)M_DIM * K_DIM];     // 8 MB

// ---------------- helpers ----------------
__device__ __forceinline__ uint32_t smem_u32(const void* p) {
    uint32_t a;
    asm("{ .reg .u64 t; cvta.to.shared.u64 t, %1; cvt.u32.u64 %0, t; }"
        : "=r"(a) : "l"(p));
    return a;
}

__device__ __forceinline__ uint32_t sw128(uint32_t off) {
    return off ^ ((off >> 3) & 0x70u);
}

// (1024+q) - 1032 = q - 8, exact in fp16, both lanes
__device__ __forceinline__ uint32_t dq_sub(uint32_t v) {
    uint32_t r;
    asm("sub.rn.f16x2 %0, %1, %2;" : "=r"(r) : "r"(v), "r"(0x64086408u));
    return r;
}

// packed word (low byte = 2 nibbles) -> fp16x2 {low = even k (hi nibble),
// high = odd k (lo nibble)}, value q-8, exact
__device__ __forceinline__ uint32_t dqw(uint32_t w) {
    uint32_t t = ((w >> 4) & 0xFu) | 0x64006400u;
    t |= (w << 16) & 0x000F0000u;
    return dq_sub(t);
}

__device__ __forceinline__ void cp_async16(uint32_t dst, const void* src) {
    asm volatile("cp.async.cg.shared.global [%0], [%1], 16;"
                 :: "r"(dst), "l"(src) : "memory");
}
__device__ __forceinline__ void cp_commit() {
    asm volatile("cp.async.commit_group;" ::: "memory");
}
template <int N>
__device__ __forceinline__ void cp_wait() {
    asm volatile("cp.async.wait_group %0;" :: "n"(N) : "memory");
}

__device__ __forceinline__ void ldmatrix4(uint32_t& r0, uint32_t& r1,
                                          uint32_t& r2, uint32_t& r3,
                                          uint32_t addr) {
    asm volatile("ldmatrix.sync.aligned.m8n8.x4.shared.b16 {%0,%1,%2,%3}, [%4];"
                 : "=r"(r0), "=r"(r1), "=r"(r2), "=r"(r3) : "r"(addr));
}

__device__ __forceinline__ void hmma(float* d,
                                     uint32_t a0, uint32_t a1, uint32_t a2, uint32_t a3,
                                     uint32_t b0, uint32_t b1) {
    asm volatile(
        "mma.sync.aligned.m16n8k16.row.col.f32.f16.f16.f32 "
        "{%0,%1,%2,%3}, {%4,%5,%6,%7}, {%8,%9}, {%0,%1,%2,%3};"
        : "+f"(d[0]), "+f"(d[1]), "+f"(d[2]), "+f"(d[3])
        : "r"(a0), "r"(a1), "r"(a2), "r"(a3), "r"(b0), "r"(b1));
}

// ---------------- prepass: x f32 -> fp16 ----------------
__global__ void prep_kernel(const float* __restrict__ x) {
    int i = blockIdx.x * blockDim.x + threadIdx.x;      // float4 index
    float4 v = reinterpret_cast<const float4*>(x)[i];
    reinterpret_cast<__half2*>(g_xh)[2 * i + 0] = __floats2half2_rn(v.x, v.y);
    reinterpret_cast<__half2*>(g_xh)[2 * i + 1] = __floats2half2_rn(v.z, v.w);
}

// ---------------- HMMA GEMM with staged in-smem W dequant ----------------
__global__ __launch_bounds__(NTHREADS, 2)
void qgemm_kernel(const int* __restrict__ packed,
                  const float* __restrict__ scale, float* __restrict__ y) {
    extern __shared__ __align__(1024) char sb[];
    const uint32_t sb32 = smem_u32(sb);

    const int tid = threadIdx.x;
    const int wid = tid >> 5;
    const int lid = tid & 31;
    const int N0 = blockIdx.x * BN;
    const int M0 = blockIdx.y * BM;

    const int wm = wid >> 1;            // 0..1 : m offset wm*64
    const int wn = wid & 1;             // 0..1 : n offset wn*64

    const __half* xb = g_xh + (size_t)M0 * K_DIM;
    const unsigned* wpk = reinterpret_cast<const unsigned*>(packed);

    // B seg mapping: seg = tid + i*128 (i=0..7) -> n = seg>>3, j = seg&7
    // Bp staging slot for seg: flat at seg*16.  Thread dequants ITS OWN segs.

    float acc[4][8][4];
    #pragma unroll
    for (int i = 0; i < 4; i++)
        #pragma unroll
        for (int j = 0; j < 8; j++)
            #pragma unroll
            for (int v = 0; v < 4; v++)
                acc[i][j][v] = 0.0f;

    // ---- prologue ----
    // g0: A[0], Bp[0]->buf0, Bp[1]->buf1 ; g1: A[1]
    {
        const uint32_t As = sb32;
        #pragma unroll
        for (int i = 0; i < 8; i++) {
            int seg = tid + i * NTHREADS;
            int m = seg >> 3, j = seg & 7;
            cp_async16(As + sw128((uint32_t)(m * 128 + j * 16)),
                       xb + (size_t)m * K_DIM + j * 8);
        }
        #pragma unroll
        for (int i = 0; i < 8; i++) {
            int seg = tid + i * NTHREADS;
            int n = seg >> 3, j = seg & 7;
            cp_async16(sb32 + OFF_BP + (uint32_t)(seg * 16),
                       wpk + (size_t)(N0 + n) * KWORDS + j * 4);
            cp_async16(sb32 + OFF_BP + BP_BYTES + (uint32_t)(seg * 16),
                       wpk + (size_t)(N0 + n) * KWORDS + (KC >> 1) + j * 4);
        }
        cp_commit();                                   // g0
        const uint32_t As1 = sb32 + A_BYTES;
        #pragma unroll
        for (int i = 0; i < 8; i++) {
            int seg = tid + i * NTHREADS;
            int m = seg >> 3, j = seg & 7;
            cp_async16(As1 + sw128((uint32_t)(m * 128 + j * 16)),
                       xb + (size_t)m * K_DIM + KC + j * 8);
        }
        cp_commit();                                   // g1
    }
    // dequant Bp[0] -> Bf[0] (own segs; visible to others at first loop sync)
    cp_wait<1>();                                      // g0 complete
    #pragma unroll
    for (int i = 0; i < 8; i++) {
        int seg = tid + i * NTHREADS;
        int n = seg >> 3, j = seg & 7;
        uint4 p = *reinterpret_cast<const uint4*>(sb + OFF_BP + seg * 16);
        uint4 q;
        q.x = dqw(p.x); q.y = dqw(p.y); q.z = dqw(p.z); q.w = dqw(p.w);
        *reinterpret_cast<uint4*>(sb + OFF_BF +
            sw128((uint32_t)(n * 128 + j * 16))) = q;
    }

    const uint32_t a_warp = (uint32_t)(wm * 64 * 128);
    const uint32_t b_warp = (uint32_t)(wn * 64 * 128);
    const int ql = lid >> 3;            // 0..3
    const int qr = lid & 7;

    for (int c = 0; c < NCHUNK; c++) {
        cp_wait<1>();
        __syncthreads();               // A[c], Bf[c%2] visible to all

        // ---- fetch A[c+2] and Bp[c+2] ----
        const int fc = c + 2;
        if (fc < NCHUNK) {
            const int k0 = fc * KC;
            const uint32_t As = sb32 + (fc % ASTAGES) * A_BYTES;
            const uint32_t Bp = sb32 + OFF_BP + (fc & 1) * BP_BYTES;
            #pragma unroll
            for (int i = 0; i < 8; i++) {
                int seg = tid + i * NTHREADS;
                int m = seg >> 3, j = seg & 7;
                cp_async16(As + sw128((uint32_t)(m * 128 + j * 16)),
                           xb + (size_t)m * K_DIM + k0 + j * 8);
            }
            #pragma unroll
            for (int i = 0; i < 8; i++) {
                int seg = tid + i * NTHREADS;
                int n = seg >> 3, j = seg & 7;
                cp_async16(Bp + (uint32_t)(seg * 16),
                           wpk + (size_t)(N0 + n) * KWORDS + (k0 >> 1) + j * 4);
            }
        }
        cp_commit();
        // Bp[c+1] (committed in group g(c-1)) complete after this wait:
        cp_wait<1>();

        const bool dq = (c + 1 < NCHUNK);
        const char* dsrc = sb + OFF_BP + ((c + 1) & 1) * BP_BYTES;
        char*       ddst = sb + OFF_BF + ((c + 1) & 1) * BF_BYTES;

        // ---- compute chunk c from A[c%3], Bf[c%2], dequant interleaved ----
        {
            const uint32_t As = sb32 + (c % ASTAGES) * A_BYTES + a_warp;
            const uint32_t Bs = sb32 + OFF_BF + (c & 1) * BF_BYTES + b_warp;

            #pragma unroll
            for (int kk = 0; kk < 4; kk++) {
                uint32_t a[4][4];
                #pragma unroll
                for (int i = 0; i < 4; i++) {
                    uint32_t addr = As + sw128((uint32_t)(
                        (i * 16 + (lid & 15)) * 128 + kk * 32 + (lid >> 4) * 16));
                    ldmatrix4(a[i][0], a[i][1], a[i][2], a[i][3], addr);
                }
                uint32_t b[8][2];
                #pragma unroll
                for (int g = 0; g < 4; g++) {
                    int row = g * 16 + (ql >> 1) * 8 + qr;
                    int kh  = ql & 1;
                    uint32_t addr = Bs + sw128((uint32_t)(
                        row * 128 + kk * 32 + kh * 16));
                    ldmatrix4(b[2*g][0], b[2*g][1], b[2*g+1][0], b[2*g+1][1], addr);
                }
                #pragma unroll
                for (int i = 0; i < 4; i++)
                    #pragma unroll
                    for (int jn = 0; jn < 8; jn++)
                        hmma(acc[i][jn], a[i][0], a[i][1], a[i][2], a[i][3],
                             b[jn][0], b[jn][1]);

                // ---- dequant 2 of this thread's 8 segs (fills HMMA shadow) ----
                if (dq) {
                    #pragma unroll
                    for (int u = 0; u < 2; u++) {
                        int seg = tid + (kk * 2 + u) * NTHREADS;
                        int n = seg >> 3, j = seg & 7;
                        uint4 p = *reinterpret_cast<const uint4*>(dsrc + seg * 16);
                        uint4 q;
                        q.x = dqw(p.x); q.y = dqw(p.y);
                        q.z = dqw(p.z); q.w = dqw(p.w);
                        *reinterpret_cast<uint4*>(ddst +
                            sw128((uint32_t)(n * 128 + j * 16))) = q;
                    }
                }
            }
        }
    }

    // ---- epilogue: scale + store fp32 ----
    #pragma unroll
    for (int i = 0; i < 4; i++) {
        int m0 = M0 + wm * 64 + i * 16 + (lid >> 2);
        #pragma unroll
        for (int j = 0; j < 8; j++) {
            int n = N0 + wn * 64 + j * 8 + 2 * (lid & 3);
            float2 s = *reinterpret_cast<const float2*>(scale + n);
            float2 o0, o1;
            o0.x = acc[i][j][0] * s.x;
            o0.y = acc[i][j][1] * s.y;
            o1.x = acc[i][j][2] * s.x;
            o1.y = acc[i][j][3] * s.y;
            *reinterpret_cast<float2*>(y + (size_t)m0 * N_DIM + n) = o0;
            *reinterpret_cast<float2*>(y + (size_t)(m0 + 8) * N_DIM + n) = o1;
        }
    }
}

// ---------------- launch ----------------
extern "C" void kernel_launch(void* const* d_in, const int* in_sizes, int n_in,
                              void* d_out, int out_size) {
    const float* x      = (const float*)d_in[0];
    const int*   packed = (const int*)  d_in[1];
    const float* scale  = (const float*)d_in[2];
    float*       y      = (float*)d_out;

    prep_kernel<<<XCONV_BLOCKS, 256>>>(x);

    static bool attr_set = false;
    if (!attr_set) {
        cudaFuncSetAttribute(qgemm_kernel,
                             cudaFuncAttributeMaxDynamicSharedMemorySize, SMEM_BYTES);
        attr_set = true;
    }
    dim3 grid(N_DIM / BN, M_DIM / BM);   // (64, 4) = 256 CTAs, 2/SM
    qgemm_kernel<<<grid, NTHREADS, SMEM_BYTES>>>(packed, scale, y);
}

// round 14
// speedup vs baseline: 1.6053x; 1.6053x over previous
#include <cuda_runtime.h>
#include <cuda_fp16.h>
#include <cstdint>

// QuantizedLinear on GB300 (sm_103a harness, compute_103 virtual arch -> legacy
// mma.sync.m16n8k16 path; tcgen05 PTX rejected by ptxas at this target).
//   y[b,o] = scale[o] * sum_k x[b,k] * (q[o,k] - 8)
//
// Round 13 = Round 11 (best) with a SPLIT compute block:
//   kk=0,1 computed with both cp.async groups in flight (full MLP, no wait),
//   then cp_wait<1> (nearly free by then), then kk=2,3 with this thread's 8
//   dequant segs interleaved 4-per-sub-block into the HMMA shadows.
// R12's regression cause (wait hoisted before all compute -> pipeline depth
// collapse, MLP halved) is avoided: the wait sits mid-compute.
// Prep = x->fp16 only. No W prepass (raw packed == fp16 DRAM bytes).

static constexpr int M_DIM = 512;
static constexpr int N_DIM = 8192;
static constexpr int K_DIM = 8192;
static constexpr int KWORDS = K_DIM / 2;           // packed words per W row

static constexpr int BM = 128;
static constexpr int BN = 128;
static constexpr int KC = 64;
static constexpr int ASTAGES = 3;
static constexpr int NCHUNK = K_DIM / KC;          // 128
static constexpr int NTHREADS = 128;               // 4 warps, 2x2 of 64x64

static constexpr int A_BYTES  = BM * 128;          // 16 KB fp16 SW128
static constexpr int BP_BYTES = BN * 128;          // 16 KB packed (flat)
static constexpr int BF_BYTES = BN * 128;          // 16 KB fp16 SW128
// layout: A[3] | Bp[2] | Bf[2]
static constexpr int OFF_BP = ASTAGES * A_BYTES;            // 49152
static constexpr int OFF_BF = OFF_BP + 2 * BP_BYTES;        // 81920
static constexpr int SMEM_BYTES = OFF_BF + 2 * BF_BYTES;    // 114688 -> 2 CTAs/SM

static constexpr int XCONV_BLOCKS = (M_DIM * K_DIM / 4) / 256;   // 4096

// -------- scratch (device global; no runtime allocation) --------
__device__ __align__(16) __half g_xh[(size_t)M_DIM * K_DIM];     // 8 MB

// ---------------- helpers ----------------
__device__ __forceinline__ uint32_t smem_u32(const void* p) {
    uint32_t a;
    asm("{ .reg .u64 t; cvta.to.shared.u64 t, %1; cvt.u32.u64 %0, t; }"
        : "=r"(a) : "l"(p));
    return a;
}

__device__ __forceinline__ uint32_t sw128(uint32_t off) {
    return off ^ ((off >> 3) & 0x70u);
}

// (1024+q) - 1032 = q - 8, exact in fp16, both lanes
__device__ __forceinline__ uint32_t dq_sub(uint32_t v) {
    uint32_t r;
    asm("sub.rn.f16x2 %0, %1, %2;" : "=r"(r) : "r"(v), "r"(0x64086408u));
    return r;
}

// packed word (low byte = 2 nibbles) -> fp16x2 {low = even k (hi nibble),
// high = odd k (lo nibble)}, value q-8, exact
__device__ __forceinline__ uint32_t dqw(uint32_t w) {
    uint32_t t = ((w >> 4) & 0xFu) | 0x64006400u;
    t |= (w << 16) & 0x000F0000u;
    return dq_sub(t);
}

__device__ __forceinline__ void cp_async16(uint32_t dst, const void* src) {
    asm volatile("cp.async.cg.shared.global [%0], [%1], 16;"
                 :: "r"(dst), "l"(src) : "memory");
}
__device__ __forceinline__ void cp_commit() {
    asm volatile("cp.async.commit_group;" ::: "memory");
}
template <int N>
__device__ __forceinline__ void cp_wait() {
    asm volatile("cp.async.wait_group %0;" :: "n"(N) : "memory");
}

__device__ __forceinline__ void ldmatrix4(uint32_t& r0, uint32_t& r1,
                                          uint32_t& r2, uint32_t& r3,
                                          uint32_t addr) {
    asm volatile("ldmatrix.sync.aligned.m8n8.x4.shared.b16 {%0,%1,%2,%3}, [%4];"
                 : "=r"(r0), "=r"(r1), "=r"(r2), "=r"(r3) : "r"(addr));
}

__device__ __forceinline__ void hmma(float* d,
                                     uint32_t a0, uint32_t a1, uint32_t a2, uint32_t a3,
                                     uint32_t b0, uint32_t b1) {
    asm volatile(
        "mma.sync.aligned.m16n8k16.row.col.f32.f16.f16.f32 "
        "{%0,%1,%2,%3}, {%4,%5,%6,%7}, {%8,%9}, {%0,%1,%2,%3};"
        : "+f"(d[0]), "+f"(d[1]), "+f"(d[2]), "+f"(d[3])
        : "r"(a0), "r"(a1), "r"(a2), "r"(a3), "r"(b0), "r"(b1));
}

// ---------------- prepass: x f32 -> fp16 ----------------
__global__ void prep_kernel(const float* __restrict__ x) {
    int i = blockIdx.x * blockDim.x + threadIdx.x;      // float4 index
    float4 v = reinterpret_cast<const float4*>(x)[i];
    reinterpret_cast<__half2*>(g_xh)[2 * i + 0] = __floats2half2_rn(v.x, v.y);
    reinterpret_cast<__half2*>(g_xh)[2 * i + 1] = __floats2half2_rn(v.z, v.w);
}

// ---------------- HMMA GEMM with staged in-smem W dequant ----------------
__global__ __launch_bounds__(NTHREADS, 2)
void qgemm_kernel(const int* __restrict__ packed,
                  const float* __restrict__ scale, float* __restrict__ y) {
    extern __shared__ __align__(1024) char sb[];
    const uint32_t sb32 = smem_u32(sb);

    const int tid = threadIdx.x;
    const int wid = tid >> 5;
    const int lid = tid & 31;
    const int N0 = blockIdx.x * BN;
    const int M0 = blockIdx.y * BM;

    const int wm = wid >> 1;            // 0..1 : m offset wm*64
    const int wn = wid & 1;             // 0..1 : n offset wn*64

    const __half* xb = g_xh + (size_t)M0 * K_DIM;
    const unsigned* wpk = reinterpret_cast<const unsigned*>(packed);

    float acc[4][8][4];
    #pragma unroll
    for (int i = 0; i < 4; i++)
        #pragma unroll
        for (int j = 0; j < 8; j++)
            #pragma unroll
            for (int v = 0; v < 4; v++)
                acc[i][j][v] = 0.0f;

    // ---- prologue ----
    // g0: A[0], Bp[0]->buf0, Bp[1]->buf1 ; g1: A[1]
    {
        const uint32_t As = sb32;
        #pragma unroll
        for (int i = 0; i < 8; i++) {
            int seg = tid + i * NTHREADS;
            int m = seg >> 3, j = seg & 7;
            cp_async16(As + sw128((uint32_t)(m * 128 + j * 16)),
                       xb + (size_t)m * K_DIM + j * 8);
        }
        #pragma unroll
        for (int i = 0; i < 8; i++) {
            int seg = tid + i * NTHREADS;
            int n = seg >> 3, j = seg & 7;
            cp_async16(sb32 + OFF_BP + (uint32_t)(seg * 16),
                       wpk + (size_t)(N0 + n) * KWORDS + j * 4);
            cp_async16(sb32 + OFF_BP + BP_BYTES + (uint32_t)(seg * 16),
                       wpk + (size_t)(N0 + n) * KWORDS + (KC >> 1) + j * 4);
        }
        cp_commit();                                   // g0
        const uint32_t As1 = sb32 + A_BYTES;
        #pragma unroll
        for (int i = 0; i < 8; i++) {
            int seg = tid + i * NTHREADS;
            int m = seg >> 3, j = seg & 7;
            cp_async16(As1 + sw128((uint32_t)(m * 128 + j * 16)),
                       xb + (size_t)m * K_DIM + KC + j * 8);
        }
        cp_commit();                                   // g1
    }
    // dequant Bp[0] -> Bf[0] (own segs; visible to others at first loop sync)
    cp_wait<1>();                                      // g0 complete
    #pragma unroll
    for (int i = 0; i < 8; i++) {
        int seg = tid + i * NTHREADS;
        int n = seg >> 3, j = seg & 7;
        uint4 p = *reinterpret_cast<const uint4*>(sb + OFF_BP + seg * 16);
        uint4 q;
        q.x = dqw(p.x); q.y = dqw(p.y); q.z = dqw(p.z); q.w = dqw(p.w);
        *reinterpret_cast<uint4*>(sb + OFF_BF +
            sw128((uint32_t)(n * 128 + j * 16))) = q;
    }

    const uint32_t a_warp = (uint32_t)(wm * 64 * 128);
    const uint32_t b_warp = (uint32_t)(wn * 64 * 128);
    const int ql = lid >> 3;            // 0..3
    const int qr = lid & 7;

    for (int c = 0; c < NCHUNK; c++) {
        cp_wait<1>();
        __syncthreads();               // A[c], Bf[c%2] visible to all

        // ---- fetch A[c+2] and Bp[c+2] ----
        const int fc = c + 2;
        if (fc < NCHUNK) {
            const int k0 = fc * KC;
            const uint32_t As = sb32 + (fc % ASTAGES) * A_BYTES;
            const uint32_t Bp = sb32 + OFF_BP + (fc & 1) * BP_BYTES;
            #pragma unroll
            for (int i = 0; i < 8; i++) {
                int seg = tid + i * NTHREADS;
                int m = seg >> 3, j = seg & 7;
                cp_async16(As + sw128((uint32_t)(m * 128 + j * 16)),
                           xb + (size_t)m * K_DIM + k0 + j * 8);
            }
            #pragma unroll
            for (int i = 0; i < 8; i++) {
                int seg = tid + i * NTHREADS;
                int n = seg >> 3, j = seg & 7;
                cp_async16(Bp + (uint32_t)(seg * 16),
                           wpk + (size_t)(N0 + n) * KWORDS + (k0 >> 1) + j * 4);
            }
        }
        cp_commit();

        const uint32_t As = sb32 + (c % ASTAGES) * A_BYTES + a_warp;
        const uint32_t Bs = sb32 + OFF_BF + (c & 1) * BF_BYTES + b_warp;
        const bool dq = (c + 1 < NCHUNK);
        const char* dsrc = sb + OFF_BP + ((c + 1) & 1) * BP_BYTES;
        char*       ddst = sb + OFF_BF + ((c + 1) & 1) * BF_BYTES;

        // ---- compute kk=0,1 (both cp.async groups still in flight) ----
        #pragma unroll
        for (int kk = 0; kk < 2; kk++) {
            uint32_t a[4][4];
            #pragma unroll
            for (int i = 0; i < 4; i++) {
                uint32_t addr = As + sw128((uint32_t)(
                    (i * 16 + (lid & 15)) * 128 + kk * 32 + (lid >> 4) * 16));
                ldmatrix4(a[i][0], a[i][1], a[i][2], a[i][3], addr);
            }
            uint32_t b[8][2];
            #pragma unroll
            for (int g = 0; g < 4; g++) {
                int row = g * 16 + (ql >> 1) * 8 + qr;
                int kh  = ql & 1;
                uint32_t addr = Bs + sw128((uint32_t)(
                    row * 128 + kk * 32 + kh * 16));
                ldmatrix4(b[2*g][0], b[2*g][1], b[2*g+1][0], b[2*g+1][1], addr);
            }
            #pragma unroll
            for (int i = 0; i < 4; i++)
                #pragma unroll
                for (int jn = 0; jn < 8; jn++)
                    hmma(acc[i][jn], a[i][0], a[i][1], a[i][2], a[i][3],
                         b[jn][0], b[jn][1]);
        }

        // ---- mid-compute wait: Bp[c+1] (group g(c-1)) — nearly free by now ----
        cp_wait<1>();

        // ---- compute kk=2,3 with dequant interleaved (4 segs each) ----
        #pragma unroll
        for (int kk = 2; kk < 4; kk++) {
            uint32_t a[4][4];
            #pragma unroll
            for (int i = 0; i < 4; i++) {
                uint32_t addr = As + sw128((uint32_t)(
                    (i * 16 + (lid & 15)) * 128 + kk * 32 + (lid >> 4) * 16));
                ldmatrix4(a[i][0], a[i][1], a[i][2], a[i][3], addr);
            }
            uint32_t b[8][2];
            #pragma unroll
            for (int g = 0; g < 4; g++) {
                int row = g * 16 + (ql >> 1) * 8 + qr;
                int kh  = ql & 1;
                uint32_t addr = Bs + sw128((uint32_t)(
                    row * 128 + kk * 32 + kh * 16));
                ldmatrix4(b[2*g][0], b[2*g][1], b[2*g+1][0], b[2*g+1][1], addr);
            }
            #pragma unroll
            for (int i = 0; i < 4; i++)
                #pragma unroll
                for (int jn = 0; jn < 8; jn++)
                    hmma(acc[i][jn], a[i][0], a[i][1], a[i][2], a[i][3],
                         b[jn][0], b[jn][1]);

            if (dq) {
                #pragma unroll
                for (int u = 0; u < 4; u++) {
                    int seg = tid + ((kk - 2) * 4 + u) * NTHREADS;
                    int n = seg >> 3, j = seg & 7;
                    uint4 p = *reinterpret_cast<const uint4*>(dsrc + seg * 16);
                    uint4 q;
                    q.x = dqw(p.x); q.y = dqw(p.y);
                    q.z = dqw(p.z); q.w = dqw(p.w);
                    *reinterpret_cast<uint4*>(ddst +
                        sw128((uint32_t)(n * 128 + j * 16))) = q;
                }
            }
        }
    }

    // ---- epilogue: scale + store fp32 ----
    #pragma unroll
    for (int i = 0; i < 4; i++) {
        int m0 = M0 + wm * 64 + i * 16 + (lid >> 2);
        #pragma unroll
        for (int j = 0; j < 8; j++) {
            int n = N0 + wn * 64 + j * 8 + 2 * (lid & 3);
            float2 s = *reinterpret_cast<const float2*>(scale + n);
            float2 o0, o1;
            o0.x = acc[i][j][0] * s.x;
            o0.y = acc[i][j][1] * s.y;
            o1.x = acc[i][j][2] * s.x;
            o1.y = acc[i][j][3] * s.y;
            *reinterpret_cast<float2*>(y + (size_t)m0 * N_DIM + n) = o0;
            *reinterpret_cast<float2*>(y + (size_t)(m0 + 8) * N_DIM + n) = o1;
        }
    }
}

// ---------------- launch ----------------
extern "C" void kernel_launch(void* const* d_in, const int* in_sizes, int n_in,
                              void* d_out, int out_size) {
    const float* x      = (const float*)d_in[0];
    const int*   packed = (const int*)  d_in[1];
    const float* scale  = (const float*)d_in[2];
    float*       y      = (float*)d_out;

    prep_kernel<<<XCONV_BLOCKS, 256>>>(x);

    static bool attr_set = false;
    if (!attr_set) {
        cudaFuncSetAttribute(qgemm_kernel,
                             cudaFuncAttributeMaxDynamicSharedMemorySize, SMEM_BYTES);
        attr_set = true;
    }
    dim3 grid(N_DIM / BN, M_DIM / BM);   // (64, 4) = 256 CTAs, 2/SM
    qgemm_kernel<<<grid, NTHREADS, SMEM_BYTES>>>(packed, scale, y);
}

// round 15
// speedup vs baseline: 1.8598x; 1.1585x over previous
#include <cuda_runtime.h>
#include <cuda_fp16.h>
#include <cstdint>

// QuantizedLinear on GB300 (sm_103a harness, compute_103 virtual arch -> legacy
// mma.sync.m16n8k16 path; tcgen05 PTX rejected by ptxas at this target).
//   y[b,o] = scale[o] * sum_k x[b,k] * (q[o,k] - 8)
//
// Round 14 = exact revert to Round 11 (best: 205.6 us).
//   - prep: x f32 -> fp16 (8 MB). No W prepass: raw packed W costs the same
//     DRAM bytes as fp16 W per value, so W is dequantized inside the GEMM.
//   - GEMM: 128x128 CTA (4 warps @ 64x64), KC=64, one barrier per chunk,
//     A triple-buffered (cp.async, SW128), packed B double-buffered flat in
//     smem (cp.async, coalesced), fp16 B double-buffered SW128.
//     Each thread dequants exactly the 16B segments IT cp.async'd (self-
//     visibility after wait_group; no extra barrier, no held registers),
//     as a monolithic block AFTER the chunk's HMMAs (interleaving into the
//     kk loop was tried twice and regresses: it breaks ptxas's HMMA schedule).
//   - 2 CTAs/SM (114688 B smem), grid 256 = full-chip single wave.

static constexpr int M_DIM = 512;
static constexpr int N_DIM = 8192;
static constexpr int K_DIM = 8192;
static constexpr int KWORDS = K_DIM / 2;           // packed words per W row

static constexpr int BM = 128;
static constexpr int BN = 128;
static constexpr int KC = 64;
static constexpr int ASTAGES = 3;
static constexpr int NCHUNK = K_DIM / KC;          // 128
static constexpr int NTHREADS = 128;               // 4 warps, 2x2 of 64x64

static constexpr int A_BYTES  = BM * 128;          // 16 KB fp16 SW128
static constexpr int BP_BYTES = BN * 128;          // 16 KB packed (flat)
static constexpr int BF_BYTES = BN * 128;          // 16 KB fp16 SW128
// layout: A[3] | Bp[2] | Bf[2]
static constexpr int OFF_BP = ASTAGES * A_BYTES;            // 49152
static constexpr int OFF_BF = OFF_BP + 2 * BP_BYTES;        // 81920
static constexpr int SMEM_BYTES = OFF_BF + 2 * BF_BYTES;    // 114688 -> 2 CTAs/SM

static constexpr int XCONV_BLOCKS = (M_DIM * K_DIM / 4) / 256;   // 4096

// -------- scratch (device global; no runtime allocation) --------
__device__ __align__(16) __half g_xh[(size_t)M_DIM * K_DIM];     // 8 MB

// ---------------- helpers ----------------
__device__ __forceinline__ uint32_t smem_u32(const void* p) {
    uint32_t a;
    asm("{ .reg .u64 t; cvta.to.shared.u64 t, %1; cvt.u32.u64 %0, t; }"
        : "=r"(a) : "l"(p));
    return a;
}

__device__ __forceinline__ uint32_t sw128(uint32_t off) {
    return off ^ ((off >> 3) & 0x70u);
}

// (1024+q) - 1032 = q - 8, exact in fp16, both lanes
__device__ __forceinline__ uint32_t dq_sub(uint32_t v) {
    uint32_t r;
    asm("sub.rn.f16x2 %0, %1, %2;" : "=r"(r) : "r"(v), "r"(0x64086408u));
    return r;
}

// packed word (low byte = 2 nibbles) -> fp16x2 {low = even k (hi nibble),
// high = odd k (lo nibble)}, value q-8, exact
__device__ __forceinline__ uint32_t dqw(uint32_t w) {
    uint32_t t = ((w >> 4) & 0xFu) | 0x64006400u;
    t |= (w << 16) & 0x000F0000u;
    return dq_sub(t);
}

__device__ __forceinline__ void cp_async16(uint32_t dst, const void* src) {
    asm volatile("cp.async.cg.shared.global [%0], [%1], 16;"
                 :: "r"(dst), "l"(src) : "memory");
}
__device__ __forceinline__ void cp_commit() {
    asm volatile("cp.async.commit_group;" ::: "memory");
}
template <int N>
__device__ __forceinline__ void cp_wait() {
    asm volatile("cp.async.wait_group %0;" :: "n"(N) : "memory");
}

__device__ __forceinline__ void ldmatrix4(uint32_t& r0, uint32_t& r1,
                                          uint32_t& r2, uint32_t& r3,
                                          uint32_t addr) {
    asm volatile("ldmatrix.sync.aligned.m8n8.x4.shared.b16 {%0,%1,%2,%3}, [%4];"
                 : "=r"(r0), "=r"(r1), "=r"(r2), "=r"(r3) : "r"(addr));
}

__device__ __forceinline__ void hmma(float* d,
                                     uint32_t a0, uint32_t a1, uint32_t a2, uint32_t a3,
                                     uint32_t b0, uint32_t b1) {
    asm volatile(
        "mma.sync.aligned.m16n8k16.row.col.f32.f16.f16.f32 "
        "{%0,%1,%2,%3}, {%4,%5,%6,%7}, {%8,%9}, {%0,%1,%2,%3};"
        : "+f"(d[0]), "+f"(d[1]), "+f"(d[2]), "+f"(d[3])
        : "r"(a0), "r"(a1), "r"(a2), "r"(a3), "r"(b0), "r"(b1));
}

// ---------------- prepass: x f32 -> fp16 ----------------
__global__ void prep_kernel(const float* __restrict__ x) {
    int i = blockIdx.x * blockDim.x + threadIdx.x;      // float4 index
    float4 v = reinterpret_cast<const float4*>(x)[i];
    reinterpret_cast<__half2*>(g_xh)[2 * i + 0] = __floats2half2_rn(v.x, v.y);
    reinterpret_cast<__half2*>(g_xh)[2 * i + 1] = __floats2half2_rn(v.z, v.w);
}

// ---------------- HMMA GEMM with staged in-smem W dequant ----------------
__global__ __launch_bounds__(NTHREADS, 2)
void qgemm_kernel(const int* __restrict__ packed,
                  const float* __restrict__ scale, float* __restrict__ y) {
    extern __shared__ __align__(1024) char sb[];
    const uint32_t sb32 = smem_u32(sb);

    const int tid = threadIdx.x;
    const int wid = tid >> 5;
    const int lid = tid & 31;
    const int N0 = blockIdx.x * BN;
    const int M0 = blockIdx.y * BM;

    const int wm = wid >> 1;            // 0..1 : m offset wm*64
    const int wn = wid & 1;             // 0..1 : n offset wn*64

    const __half* xb = g_xh + (size_t)M0 * K_DIM;
    const unsigned* wpk = reinterpret_cast<const unsigned*>(packed);

    // B seg mapping: seg = tid + i*128 (i=0..7) -> n = seg>>3, j = seg&7
    // Bp staging slot for seg: flat at seg*16.  Thread dequants ITS OWN segs.

    float acc[4][8][4];
    #pragma unroll
    for (int i = 0; i < 4; i++)
        #pragma unroll
        for (int j = 0; j < 8; j++)
            #pragma unroll
            for (int v = 0; v < 4; v++)
                acc[i][j][v] = 0.0f;

    // ---- prologue ----
    // g0: A[0], Bp[0]->buf0, Bp[1]->buf1 ; g1: A[1]
    {
        const uint32_t As = sb32;
        #pragma unroll
        for (int i = 0; i < 8; i++) {
            int seg = tid + i * NTHREADS;
            int m = seg >> 3, j = seg & 7;
            cp_async16(As + sw128((uint32_t)(m * 128 + j * 16)),
                       xb + (size_t)m * K_DIM + j * 8);
        }
        #pragma unroll
        for (int i = 0; i < 8; i++) {
            int seg = tid + i * NTHREADS;
            int n = seg >> 3, j = seg & 7;
            cp_async16(sb32 + OFF_BP + (uint32_t)(seg * 16),
                       wpk + (size_t)(N0 + n) * KWORDS + j * 4);
            cp_async16(sb32 + OFF_BP + BP_BYTES + (uint32_t)(seg * 16),
                       wpk + (size_t)(N0 + n) * KWORDS + (KC >> 1) + j * 4);
        }
        cp_commit();                                   // g0
        const uint32_t As1 = sb32 + A_BYTES;
        #pragma unroll
        for (int i = 0; i < 8; i++) {
            int seg = tid + i * NTHREADS;
            int m = seg >> 3, j = seg & 7;
            cp_async16(As1 + sw128((uint32_t)(m * 128 + j * 16)),
                       xb + (size_t)m * K_DIM + KC + j * 8);
        }
        cp_commit();                                   // g1
    }
    // dequant Bp[0] -> Bf[0] (own segs; visible to others at first loop sync)
    cp_wait<1>();                                      // g0 complete
    #pragma unroll
    for (int i = 0; i < 8; i++) {
        int seg = tid + i * NTHREADS;
        int n = seg >> 3, j = seg & 7;
        uint4 p = *reinterpret_cast<const uint4*>(sb + OFF_BP + seg * 16);
        uint4 q;
        q.x = dqw(p.x); q.y = dqw(p.y); q.z = dqw(p.z); q.w = dqw(p.w);
        *reinterpret_cast<uint4*>(sb + OFF_BF +
            sw128((uint32_t)(n * 128 + j * 16))) = q;
    }

    const uint32_t a_warp = (uint32_t)(wm * 64 * 128);
    const uint32_t b_warp = (uint32_t)(wn * 64 * 128);
    const int ql = lid >> 3;            // 0..3
    const int qr = lid & 7;

    for (int c = 0; c < NCHUNK; c++) {
        cp_wait<1>();
        __syncthreads();               // A[c], Bf[c%2] visible to all

        // ---- fetch A[c+2] and Bp[c+2] ----
        const int fc = c + 2;
        if (fc < NCHUNK) {
            const int k0 = fc * KC;
            const uint32_t As = sb32 + (fc % ASTAGES) * A_BYTES;
            const uint32_t Bp = sb32 + OFF_BP + (fc & 1) * BP_BYTES;
            #pragma unroll
            for (int i = 0; i < 8; i++) {
                int seg = tid + i * NTHREADS;
                int m = seg >> 3, j = seg & 7;
                cp_async16(As + sw128((uint32_t)(m * 128 + j * 16)),
                           xb + (size_t)m * K_DIM + k0 + j * 8);
            }
            #pragma unroll
            for (int i = 0; i < 8; i++) {
                int seg = tid + i * NTHREADS;
                int n = seg >> 3, j = seg & 7;
                cp_async16(Bp + (uint32_t)(seg * 16),
                           wpk + (size_t)(N0 + n) * KWORDS + (k0 >> 1) + j * 4);
            }
        }
        cp_commit();

        // ---- compute chunk c from A[c%3], Bf[c%2] ----
        {
            const uint32_t As = sb32 + (c % ASTAGES) * A_BYTES + a_warp;
            const uint32_t Bs = sb32 + OFF_BF + (c & 1) * BF_BYTES + b_warp;

            #pragma unroll
            for (int kk = 0; kk < 4; kk++) {
                uint32_t a[4][4];
                #pragma unroll
                for (int i = 0; i < 4; i++) {
                    uint32_t addr = As + sw128((uint32_t)(
                        (i * 16 + (lid & 15)) * 128 + kk * 32 + (lid >> 4) * 16));
                    ldmatrix4(a[i][0], a[i][1], a[i][2], a[i][3], addr);
                }
                uint32_t b[8][2];
                #pragma unroll
                for (int g = 0; g < 4; g++) {
                    int row = g * 16 + (ql >> 1) * 8 + qr;
                    int kh  = ql & 1;
                    uint32_t addr = Bs + sw128((uint32_t)(
                        row * 128 + kk * 32 + kh * 16));
                    ldmatrix4(b[2*g][0], b[2*g][1], b[2*g+1][0], b[2*g+1][1], addr);
                }
                #pragma unroll
                for (int i = 0; i < 4; i++)
                    #pragma unroll
                    for (int jn = 0; jn < 8; jn++)
                        hmma(acc[i][jn], a[i][0], a[i][1], a[i][2], a[i][3],
                             b[jn][0], b[jn][1]);
            }
        }

        // ---- dequant Bp[c+1] -> Bf[(c+1)%2] (own segs only) ----
        if (c + 1 < NCHUNK) {
            cp_wait<1>();              // group carrying Bp[c+1] (iter c-1 / g0) done
            const char* src = sb + OFF_BP + ((c + 1) & 1) * BP_BYTES;
            char*       dst = sb + OFF_BF + ((c + 1) & 1) * BF_BYTES;
            #pragma unroll
            for (int i = 0; i < 8; i++) {
                int seg = tid + i * NTHREADS;
                int n = seg >> 3, j = seg & 7;
                uint4 p = *reinterpret_cast<const uint4*>(src + seg * 16);
                uint4 q;
                q.x = dqw(p.x); q.y = dqw(p.y); q.z = dqw(p.z); q.w = dqw(p.w);
                *reinterpret_cast<uint4*>(dst +
                    sw128((uint32_t)(n * 128 + j * 16))) = q;
            }
        }
    }

    // ---- epilogue: scale + store fp32 ----
    #pragma unroll
    for (int i = 0; i < 4; i++) {
        int m0 = M0 + wm * 64 + i * 16 + (lid >> 2);
        #pragma unroll
        for (int j = 0; j < 8; j++) {
            int n = N0 + wn * 64 + j * 8 + 2 * (lid & 3);
            float2 s = *reinterpret_cast<const float2*>(scale + n);
            float2 o0, o1;
            o0.x = acc[i][j][0] * s.x;
            o0.y = acc[i][j][1] * s.y;
            o1.x = acc[i][j][2] * s.x;
            o1.y = acc[i][j][3] * s.y;
            *reinterpret_cast<float2*>(y + (size_t)m0 * N_DIM + n) = o0;
            *reinterpret_cast<float2*>(y + (size_t)(m0 + 8) * N_DIM + n) = o1;
        }
    }
}

// ---------------- launch ----------------
extern "C" void kernel_launch(void* const* d_in, const int* in_sizes, int n_in,
                              void* d_out, int out_size) {
    const float* x      = (const float*)d_in[0];
    const int*   packed = (const int*)  d_in[1];
    const float* scale  = (const float*)d_in[2];
    float*       y      = (float*)d_out;

    prep_kernel<<<XCONV_BLOCKS, 256>>>(x);

    static bool attr_set = false;
    if (!attr_set) {
        cudaFuncSetAttribute(qgemm_kernel,
                             cudaFuncAttributeMaxDynamicSharedMemorySize, SMEM_BYTES);
        attr_set = true;
    }
    dim3 grid(N_DIM / BN, M_DIM / BM);   // (64, 4) = 256 CTAs, 2/SM
    qgemm_kernel<<<grid, NTHREADS, SMEM_BYTES>>>(packed, scale, y);
}

// round 16
// speedup vs baseline: 1.8788x; 1.0102x over previous
#include <cuda_runtime.h>
#include <cuda_fp16.h>
#include <cstdint>

// QuantizedLinear on GB300 (sm_103a harness, compute_103 virtual arch -> legacy
// mma.sync.m16n8k16 path; tcgen05 PTX rejected by ptxas at this target).
//   y[b,o] = scale[o] * sum_k x[b,k] * (q[o,k] - 8)
//
// Round 15 = Round 11/14 skeleton (best, reproduced 205.1/205.6 us) +
//   (a) PRMT-based dequant: SHR+PRMT+LOP3+sub.f16x2 (4 ops/word vs 5),
//       exploiting that packed words are 0..255 (upper bytes zero).
//   (b) prep kernel with MLP=4 (4 strided float4 per thread).
// Structure: x->fp16 prep; no W prepass (raw packed == fp16 DRAM bytes);
// GEMM 128x128 CTA (4 warps @ 64x64), KC=64, one barrier/chunk, A[3] SW128
// cp.async, packed B[2] flat cp.async, fp16 B[2] SW128, self-owned-segment
// dequant as a monolithic block AFTER the chunk's HMMAs. 2 CTAs/SM, grid 256.

static constexpr int M_DIM = 512;
static constexpr int N_DIM = 8192;
static constexpr int K_DIM = 8192;
static constexpr int KWORDS = K_DIM / 2;           // packed words per W row

static constexpr int BM = 128;
static constexpr int BN = 128;
static constexpr int KC = 64;
static constexpr int ASTAGES = 3;
static constexpr int NCHUNK = K_DIM / KC;          // 128
static constexpr int NTHREADS = 128;               // 4 warps, 2x2 of 64x64

static constexpr int A_BYTES  = BM * 128;          // 16 KB fp16 SW128
static constexpr int BP_BYTES = BN * 128;          // 16 KB packed (flat)
static constexpr int BF_BYTES = BN * 128;          // 16 KB fp16 SW128
// layout: A[3] | Bp[2] | Bf[2]
static constexpr int OFF_BP = ASTAGES * A_BYTES;            // 49152
static constexpr int OFF_BF = OFF_BP + 2 * BP_BYTES;        // 81920
static constexpr int SMEM_BYTES = OFF_BF + 2 * BF_BYTES;    // 114688 -> 2 CTAs/SM

// prep: 1M float4 total; 4 per thread, strided
static constexpr int PREP_THREADS_TOT = (M_DIM * K_DIM / 4) / 4;  // 262144
static constexpr int PREP_BLOCKS = PREP_THREADS_TOT / 256;        // 1024

// -------- scratch (device global; no runtime allocation) --------
__device__ __align__(16) __half g_xh[(size_t)M_DIM * K_DIM];     // 8 MB

// ---------------- helpers ----------------
__device__ __forceinline__ uint32_t smem_u32(const void* p) {
    uint32_t a;
    asm("{ .reg .u64 t; cvta.to.shared.u64 t, %1; cvt.u32.u64 %0, t; }"
        : "=r"(a) : "l"(p));
    return a;
}

__device__ __forceinline__ uint32_t sw128(uint32_t off) {
    return off ^ ((off >> 3) & 0x70u);
}

// (1024+q) - 1032 = q - 8, exact in fp16, both lanes
__device__ __forceinline__ uint32_t dq_sub(uint32_t v) {
    uint32_t r;
    asm("sub.rn.f16x2 %0, %1, %2;" : "=r"(r) : "r"(v), "r"(0x64086408u));
    return r;
}

// packed word (value 0..255: upper bytes ZERO) -> fp16x2
//   {low lane = hi nibble (even k), high lane = lo nibble (odd k)}, q-8 exact.
// s = w>>4 -> s.byte0 = b>>4.  PRMT(s,w,0x7430) = [b>>4, 0, b, 0].
// One LOP3 masks the nibbles and ORs the 0x6400 exponent; sub finishes.
__device__ __forceinline__ uint32_t dqw(uint32_t w) {
    uint32_t s = w >> 4;
    uint32_t r;
    asm("prmt.b32 %0, %1, %2, 0x7430;" : "=r"(r) : "r"(s), "r"(w));
    r = (r & 0x000F000Fu) | 0x64006400u;     // single LOP3
    return dq_sub(r);
}

__device__ __forceinline__ void cp_async16(uint32_t dst, const void* src) {
    asm volatile("cp.async.cg.shared.global [%0], [%1], 16;"
                 :: "r"(dst), "l"(src) : "memory");
}
__device__ __forceinline__ void cp_commit() {
    asm volatile("cp.async.commit_group;" ::: "memory");
}
template <int N>
__device__ __forceinline__ void cp_wait() {
    asm volatile("cp.async.wait_group %0;" :: "n"(N) : "memory");
}

__device__ __forceinline__ void ldmatrix4(uint32_t& r0, uint32_t& r1,
                                          uint32_t& r2, uint32_t& r3,
                                          uint32_t addr) {
    asm volatile("ldmatrix.sync.aligned.m8n8.x4.shared.b16 {%0,%1,%2,%3}, [%4];"
                 : "=r"(r0), "=r"(r1), "=r"(r2), "=r"(r3) : "r"(addr));
}

__device__ __forceinline__ void hmma(float* d,
                                     uint32_t a0, uint32_t a1, uint32_t a2, uint32_t a3,
                                     uint32_t b0, uint32_t b1) {
    asm volatile(
        "mma.sync.aligned.m16n8k16.row.col.f32.f16.f16.f32 "
        "{%0,%1,%2,%3}, {%4,%5,%6,%7}, {%8,%9}, {%0,%1,%2,%3};"
        : "+f"(d[0]), "+f"(d[1]), "+f"(d[2]), "+f"(d[3])
        : "r"(a0), "r"(a1), "r"(a2), "r"(a3), "r"(b0), "r"(b1));
}

// ---------------- prepass: x f32 -> fp16 (MLP=4) ----------------
__global__ void prep_kernel(const float* __restrict__ x) {
    int t = blockIdx.x * blockDim.x + threadIdx.x;
    #pragma unroll
    for (int u = 0; u < 4; u++) {
        int i = t + u * PREP_THREADS_TOT;              // float4 index, strided
        float4 v = reinterpret_cast<const float4*>(x)[i];
        reinterpret_cast<__half2*>(g_xh)[2 * i + 0] = __floats2half2_rn(v.x, v.y);
        reinterpret_cast<__half2*>(g_xh)[2 * i + 1] = __floats2half2_rn(v.z, v.w);
    }
}

// ---------------- HMMA GEMM with staged in-smem W dequant ----------------
__global__ __launch_bounds__(NTHREADS, 2)
void qgemm_kernel(const int* __restrict__ packed,
                  const float* __restrict__ scale, float* __restrict__ y) {
    extern __shared__ __align__(1024) char sb[];
    const uint32_t sb32 = smem_u32(sb);

    const int tid = threadIdx.x;
    const int wid = tid >> 5;
    const int lid = tid & 31;
    const int N0 = blockIdx.x * BN;
    const int M0 = blockIdx.y * BM;

    const int wm = wid >> 1;            // 0..1 : m offset wm*64
    const int wn = wid & 1;             // 0..1 : n offset wn*64

    const __half* xb = g_xh + (size_t)M0 * K_DIM;
    const unsigned* wpk = reinterpret_cast<const unsigned*>(packed);

    // B seg mapping: seg = tid + i*128 (i=0..7) -> n = seg>>3, j = seg&7
    // Bp staging slot for seg: flat at seg*16.  Thread dequants ITS OWN segs.

    float acc[4][8][4];
    #pragma unroll
    for (int i = 0; i < 4; i++)
        #pragma unroll
        for (int j = 0; j < 8; j++)
            #pragma unroll
            for (int v = 0; v < 4; v++)
                acc[i][j][v] = 0.0f;

    // ---- prologue ----
    // g0: A[0], Bp[0]->buf0, Bp[1]->buf1 ; g1: A[1]
    {
        const uint32_t As = sb32;
        #pragma unroll
        for (int i = 0; i < 8; i++) {
            int seg = tid + i * NTHREADS;
            int m = seg >> 3, j = seg & 7;
            cp_async16(As + sw128((uint32_t)(m * 128 + j * 16)),
                       xb + (size_t)m * K_DIM + j * 8);
        }
        #pragma unroll
        for (int i = 0; i < 8; i++) {
            int seg = tid + i * NTHREADS;
            int n = seg >> 3, j = seg & 7;
            cp_async16(sb32 + OFF_BP + (uint32_t)(seg * 16),
                       wpk + (size_t)(N0 + n) * KWORDS + j * 4);
            cp_async16(sb32 + OFF_BP + BP_BYTES + (uint32_t)(seg * 16),
                       wpk + (size_t)(N0 + n) * KWORDS + (KC >> 1) + j * 4);
        }
        cp_commit();                                   // g0
        const uint32_t As1 = sb32 + A_BYTES;
        #pragma unroll
        for (int i = 0; i < 8; i++) {
            int seg = tid + i * NTHREADS;
            int m = seg >> 3, j = seg & 7;
            cp_async16(As1 + sw128((uint32_t)(m * 128 + j * 16)),
                       xb + (size_t)m * K_DIM + KC + j * 8);
        }
        cp_commit();                                   // g1
    }
    // dequant Bp[0] -> Bf[0] (own segs; visible to others at first loop sync)
    cp_wait<1>();                                      // g0 complete
    #pragma unroll
    for (int i = 0; i < 8; i++) {
        int seg = tid + i * NTHREADS;
        int n = seg >> 3, j = seg & 7;
        uint4 p = *reinterpret_cast<const uint4*>(sb + OFF_BP + seg * 16);
        uint4 q;
        q.x = dqw(p.x); q.y = dqw(p.y); q.z = dqw(p.z); q.w = dqw(p.w);
        *reinterpret_cast<uint4*>(sb + OFF_BF +
            sw128((uint32_t)(n * 128 + j * 16))) = q;
    }

    const uint32_t a_warp = (uint32_t)(wm * 64 * 128);
    const uint32_t b_warp = (uint32_t)(wn * 64 * 128);
    const int ql = lid >> 3;            // 0..3
    const int qr = lid & 7;

    for (int c = 0; c < NCHUNK; c++) {
        cp_wait<1>();
        __syncthreads();               // A[c], Bf[c%2] visible to all

        // ---- fetch A[c+2] and Bp[c+2] ----
        const int fc = c + 2;
        if (fc < NCHUNK) {
            const int k0 = fc * KC;
            const uint32_t As = sb32 + (fc % ASTAGES) * A_BYTES;
            const uint32_t Bp = sb32 + OFF_BP + (fc & 1) * BP_BYTES;
            #pragma unroll
            for (int i = 0; i < 8; i++) {
                int seg = tid + i * NTHREADS;
                int m = seg >> 3, j = seg & 7;
                cp_async16(As + sw128((uint32_t)(m * 128 + j * 16)),
                           xb + (size_t)m * K_DIM + k0 + j * 8);
            }
            #pragma unroll
            for (int i = 0; i < 8; i++) {
                int seg = tid + i * NTHREADS;
                int n = seg >> 3, j = seg & 7;
                cp_async16(Bp + (uint32_t)(seg * 16),
                           wpk + (size_t)(N0 + n) * KWORDS + (k0 >> 1) + j * 4);
            }
        }
        cp_commit();

        // ---- compute chunk c from A[c%3], Bf[c%2] ----
        {
            const uint32_t As = sb32 + (c % ASTAGES) * A_BYTES + a_warp;
            const uint32_t Bs = sb32 + OFF_BF + (c & 1) * BF_BYTES + b_warp;

            #pragma unroll
            for (int kk = 0; kk < 4; kk++) {
                uint32_t a[4][4];
                #pragma unroll
                for (int i = 0; i < 4; i++) {
                    uint32_t addr = As + sw128((uint32_t)(
                        (i * 16 + (lid & 15)) * 128 + kk * 32 + (lid >> 4) * 16));
                    ldmatrix4(a[i][0], a[i][1], a[i][2], a[i][3], addr);
                }
                uint32_t b[8][2];
                #pragma unroll
                for (int g = 0; g < 4; g++) {
                    int row = g * 16 + (ql >> 1) * 8 + qr;
                    int kh  = ql & 1;
                    uint32_t addr = Bs + sw128((uint32_t)(
                        row * 128 + kk * 32 + kh * 16));
                    ldmatrix4(b[2*g][0], b[2*g][1], b[2*g+1][0], b[2*g+1][1], addr);
                }
                #pragma unroll
                for (int i = 0; i < 4; i++)
                    #pragma unroll
                    for (int jn = 0; jn < 8; jn++)
                        hmma(acc[i][jn], a[i][0], a[i][1], a[i][2], a[i][3],
                             b[jn][0], b[jn][1]);
            }
        }

        // ---- dequant Bp[c+1] -> Bf[(c+1)%2] (own segs only) ----
        if (c + 1 < NCHUNK) {
            cp_wait<1>();              // group carrying Bp[c+1] (iter c-1 / g0) done
            const char* src = sb + OFF_BP + ((c + 1) & 1) * BP_BYTES;
            char*       dst = sb + OFF_BF + ((c + 1) & 1) * BF_BYTES;
            #pragma unroll
            for (int i = 0; i < 8; i++) {
                int seg = tid + i * NTHREADS;
                int n = seg >> 3, j = seg & 7;
                uint4 p = *reinterpret_cast<const uint4*>(src + seg * 16);
                uint4 q;
                q.x = dqw(p.x); q.y = dqw(p.y); q.z = dqw(p.z); q.w = dqw(p.w);
                *reinterpret_cast<uint4*>(dst +
                    sw128((uint32_t)(n * 128 + j * 16))) = q;
            }
        }
    }

    // ---- epilogue: scale + store fp32 ----
    #pragma unroll
    for (int i = 0; i < 4; i++) {
        int m0 = M0 + wm * 64 + i * 16 + (lid >> 2);
        #pragma unroll
        for (int j = 0; j < 8; j++) {
            int n = N0 + wn * 64 + j * 8 + 2 * (lid & 3);
            float2 s = *reinterpret_cast<const float2*>(scale + n);
            float2 o0, o1;
            o0.x = acc[i][j][0] * s.x;
            o0.y = acc[i][j][1] * s.y;
            o1.x = acc[i][j][2] * s.x;
            o1.y = acc[i][j][3] * s.y;
            *reinterpret_cast<float2*>(y + (size_t)m0 * N_DIM + n) = o0;
            *reinterpret_cast<float2*>(y + (size_t)(m0 + 8) * N_DIM + n) = o1;
        }
    }
}

// ---------------- launch ----------------
extern "C" void kernel_launch(void* const* d_in, const int* in_sizes, int n_in,
                              void* d_out, int out_size) {
    const float* x      = (const float*)d_in[0];
    const int*   packed = (const int*)  d_in[1];
    const float* scale  = (const float*)d_in[2];
    float*       y      = (float*)d_out;

    prep_kernel<<<PREP_BLOCKS, 256>>>(x);

    static bool attr_set = false;
    if (!attr_set) {
        cudaFuncSetAttribute(qgemm_kernel,
                             cudaFuncAttributeMaxDynamicSharedMemorySize, SMEM_BYTES);
        attr_set = true;
    }
    dim3 grid(N_DIM / BN, M_DIM / BM);   // (64, 4) = 256 CTAs, 2/SM
    qgemm_kernel<<<grid, NTHREADS, SMEM_BYTES>>>(packed, scale, y);
}